// round 1
// baseline (speedup 1.0000x reference)
#include <cuda_runtime.h>
#include <cuda_bf16.h>

// Problem constants (fixed by the dataset).
#define E_CNT 500000
#define P_CNT 4000000
#define D_DIM 64
#define U_DIM 64

// Scratch: segment-sum accumulator [E, D] = 128 MB. Device global (no alloc).
__device__ float g_agg[(size_t)E_CNT * D_DIM];

// ---------------------------------------------------------------------------
// Kernel 1: zero the accumulator (128 MB of stores, ~22 us at HBM rate).
// ---------------------------------------------------------------------------
__global__ void zero_agg_kernel() {
    const size_t n4 = (size_t)E_CNT * D_DIM / 4;
    float4 z = make_float4(0.f, 0.f, 0.f, 0.f);
    float4* p = reinterpret_cast<float4*>(g_agg);
    for (size_t i = (size_t)blockIdx.x * blockDim.x + threadIdx.x; i < n4;
         i += (size_t)gridDim.x * blockDim.x)
        p[i] = z;
}

// ---------------------------------------------------------------------------
// Kernel 2: gather + scatter-add.
// 16 threads per edge: each thread handles one float4 (16 B) of the 256 B row.
// Consecutive threads read consecutive 16 B of the source row -> coalesced
// 64 B gathers per quarter-warp. Accumulate with vector red.global.add.v4.f32
// (sm_90+): 64M vector reductions instead of 256M scalar atomics.
// ---------------------------------------------------------------------------
__global__ void __launch_bounds__(256) scatter_kernel(
    const float4* __restrict__ feat4, const int* __restrict__ nbr) {
    long long t = (long long)blockIdx.x * blockDim.x + threadIdx.x;
    int p = (int)(t >> 4);
    int q = (int)(t & 15);
    if (p >= P_CNT) return;
    int dst = __ldg(&nbr[2 * p + 0]);
    int src = __ldg(&nbr[2 * p + 1]);
    float4 v = __ldg(&feat4[(size_t)src * 16 + q]);
    float* ap = g_agg + ((size_t)dst * 64 + (size_t)q * 4);
    asm volatile("red.global.add.v4.f32 [%0], {%1, %2, %3, %4};"
                 :: "l"(ap), "f"(v.x), "f"(v.y), "f"(v.z), "f"(v.w)
                 : "memory");
}

// ---------------------------------------------------------------------------
// Kernel 3: out = agg @ K + bias.
// 256 threads = 4 groups of 64. Thread u in a group owns output column u and
// keeps K[:,u] in 64 registers (loaded once, coalesced, L1/L2-hit for all but
// the first block). Each group processes 8 rows: rows staged in smem
// (coalesced float4 global loads), then broadcast-LDS128 feeds 4 FFMAs each.
// FMA-bound by design: 512 FFMA + 128 broadcast LDS128 per thread.
// ---------------------------------------------------------------------------
__global__ void __launch_bounds__(256) gemm_kernel(
    const float* __restrict__ Kmat, const float* __restrict__ bias,
    float* __restrict__ out) {
    __shared__ float S[4][8 * 64];  // 4 groups x 8 rows x 64 cols = 8 KB

    int g = threadIdx.x >> 6;   // group 0..3
    int u = threadIdx.x & 63;   // output column

    // K column in registers: Kreg[k] = K[k][u]
    float Kreg[64];
#pragma unroll
    for (int k = 0; k < 64; k++) Kreg[k] = __ldg(&Kmat[k * U_DIM + u]);
    float b = __ldg(&bias[u]);

    int rowBase = blockIdx.x * 32 + g * 8;

    // Stage 8 rows (512 floats = 128 float4) into smem, coalesced.
    const float4* src = reinterpret_cast<const float4*>(g_agg + (size_t)rowBase * 64);
    float4* S4 = reinterpret_cast<float4*>(S[g]);
    S4[u]      = src[u];
    S4[u + 64] = src[u + 64];
    __syncthreads();

    float acc[8];
#pragma unroll
    for (int r = 0; r < 8; r++) acc[r] = 0.f;

#pragma unroll
    for (int k4 = 0; k4 < 16; k4++) {
#pragma unroll
        for (int r = 0; r < 8; r++) {
            // Broadcast load: all 64 threads in the group read the same addr.
            float4 a = reinterpret_cast<const float4*>(S[g] + r * 64)[k4];
            acc[r] = fmaf(a.x, Kreg[4 * k4 + 0],
                     fmaf(a.y, Kreg[4 * k4 + 1],
                     fmaf(a.z, Kreg[4 * k4 + 2],
                     fmaf(a.w, Kreg[4 * k4 + 3], acc[r]))));
        }
    }

#pragma unroll
    for (int r = 0; r < 8; r++)
        out[(size_t)(rowBase + r) * U_DIM + u] = acc[r] + b;
}

// ---------------------------------------------------------------------------
// Launch: zero -> scatter -> gemm on the default stream (graph-capturable,
// no allocs, no syncs).
// ---------------------------------------------------------------------------
extern "C" void kernel_launch(void* const* d_in, const int* in_sizes, int n_in,
                              void* d_out, int out_size) {
    const float* feat = (const float*)d_in[0];   // [E, 64] fp32
    const int*   nbr  = (const int*)d_in[1];     // [P, 2]  int32
    const float* Kmat = (const float*)d_in[2];   // [64, 64] fp32
    const float* bias = (const float*)d_in[3];   // [64] fp32
    float* out = (float*)d_out;                  // [E, 64] fp32

    zero_agg_kernel<<<2048, 256>>>();

    long long total = (long long)P_CNT * 16;
    int blocks = (int)((total + 255) / 256);     // 250000
    scatter_kernel<<<blocks, 256>>>((const float4*)feat, nbr);

    gemm_kernel<<<E_CNT / 32, 256>>>(Kmat, bias, out);
}

// round 5
// speedup vs baseline: 1.3532x; 1.3532x over previous
#include <cuda_runtime.h>
#include <cuda_bf16.h>

// Problem constants (fixed by the dataset).
#define E_CNT 500000
#define P_CNT 4000000
#define D_DIM 64
#define U_DIM 64

#define SCAN_BLK 1024
#define NSCAN ((E_CNT + SCAN_BLK - 1) / SCAN_BLK)   // 489

// Device scratch (no allocs allowed). Total ~38 MB.
__device__ int g_cnt[E_CNT];        // per-dst edge counts
__device__ int g_off[E_CNT];        // exclusive prefix (global)
__device__ int g_cursor[E_CNT];     // running cursors for reorder
__device__ int g_blocksum[NSCAN];
__device__ int g_blockoff[NSCAN];
__device__ int g_srcs[P_CNT];       // src indices sorted by dst

// ---------------------------------------------------------------------------
// 1. Zero the histogram.
// ---------------------------------------------------------------------------
__global__ void k_zero_cnt() {
    int i = blockIdx.x * blockDim.x + threadIdx.x;       // int4 index
    const int n4 = E_CNT / 4;                            // 125000
    if (i < n4) reinterpret_cast<int4*>(g_cnt)[i] = make_int4(0, 0, 0, 0);
}

// ---------------------------------------------------------------------------
// 2. Histogram of destinations.
// ---------------------------------------------------------------------------
__global__ void __launch_bounds__(256) k_hist(const int2* __restrict__ nbr) {
    int p = blockIdx.x * blockDim.x + threadIdx.x;
    if (p < P_CNT) atomicAdd(&g_cnt[__ldg(&nbr[p]).x], 1);
}

// ---------------------------------------------------------------------------
// 3. Block-local exclusive scan (Hillis-Steele, 1024/block) + block sums.
// ---------------------------------------------------------------------------
__global__ void __launch_bounds__(SCAN_BLK) k_scan_block() {
    __shared__ int tmp[SCAN_BLK];
    int t = threadIdx.x;
    int gid = blockIdx.x * SCAN_BLK + t;
    int v = (gid < E_CNT) ? g_cnt[gid] : 0;
    tmp[t] = v;
    __syncthreads();
#pragma unroll
    for (int d = 1; d < SCAN_BLK; d <<= 1) {
        int x = (t >= d) ? tmp[t - d] : 0;
        __syncthreads();
        tmp[t] += x;
        __syncthreads();
    }
    if (gid < E_CNT) g_off[gid] = tmp[t] - v;            // exclusive, block-local
    if (t == SCAN_BLK - 1) g_blocksum[blockIdx.x] = tmp[t];
}

// ---------------------------------------------------------------------------
// 4. Scan of block sums (single block).
// ---------------------------------------------------------------------------
__global__ void __launch_bounds__(SCAN_BLK) k_scan_sums() {
    __shared__ int tmp[SCAN_BLK];
    int t = threadIdx.x;
    int v = (t < NSCAN) ? g_blocksum[t] : 0;
    tmp[t] = v;
    __syncthreads();
#pragma unroll
    for (int d = 1; d < SCAN_BLK; d <<= 1) {
        int x = (t >= d) ? tmp[t - d] : 0;
        __syncthreads();
        tmp[t] += x;
        __syncthreads();
    }
    if (t < NSCAN) g_blockoff[t] = tmp[t] - v;           // exclusive
}

// ---------------------------------------------------------------------------
// 5. Globalize offsets; init cursors.
// ---------------------------------------------------------------------------
__global__ void __launch_bounds__(256) k_scan_add() {
    int i = blockIdx.x * blockDim.x + threadIdx.x;
    if (i < E_CNT) {
        int o = g_off[i] + g_blockoff[i >> 10];
        g_off[i] = o;
        g_cursor[i] = o;
    }
}

// ---------------------------------------------------------------------------
// 6. Reorder: scatter src ids into dst-sorted order.
// ---------------------------------------------------------------------------
__global__ void __launch_bounds__(256) k_reorder(const int2* __restrict__ nbr) {
    int p = blockIdx.x * blockDim.x + threadIdx.x;
    if (p < P_CNT) {
        int2 e = __ldg(&nbr[p]);
        int pos = atomicAdd(&g_cursor[e.x], 1);
        g_srcs[pos] = e.y;
    }
}

// ---------------------------------------------------------------------------
// 7. Fused segmented-sum + GEMM + bias. 256 threads = 8 warps per block.
//    Phase A: warp w aggregates dst row (block*8 + w); lane owns 2 columns
//    (float2), 4-way unrolled gathers for MLP. No atomics, no accumulator
//    buffer. Phase B: register-resident K column GEMM (as round 1), writing
//    d_out once.
// ---------------------------------------------------------------------------
__global__ void __launch_bounds__(256) k_fused(
    const float2* __restrict__ F2, const float* __restrict__ Kmat,
    const float* __restrict__ bias, float* __restrict__ out) {
    __shared__ float S[8][64];

    int warp = threadIdx.x >> 5;
    int lane = threadIdx.x & 31;
    int dst = blockIdx.x * 8 + warp;

    // ---- Phase A: gather + accumulate ----
    int s = __ldg(&g_off[dst]);
    int e = (dst == E_CNT - 1) ? P_CNT : __ldg(&g_off[dst + 1]);

    float ax = 0.f, ay = 0.f;
    int i = s;
    for (; i + 4 <= e; i += 4) {
        int s0 = __ldg(&g_srcs[i + 0]);
        int s1 = __ldg(&g_srcs[i + 1]);
        int s2 = __ldg(&g_srcs[i + 2]);
        int s3 = __ldg(&g_srcs[i + 3]);
        float2 v0 = __ldg(&F2[(size_t)s0 * 32 + lane]);
        float2 v1 = __ldg(&F2[(size_t)s1 * 32 + lane]);
        float2 v2 = __ldg(&F2[(size_t)s2 * 32 + lane]);
        float2 v3 = __ldg(&F2[(size_t)s3 * 32 + lane]);
        ax += (v0.x + v1.x) + (v2.x + v3.x);
        ay += (v0.y + v1.y) + (v2.y + v3.y);
    }
    for (; i < e; i++) {
        int s0 = __ldg(&g_srcs[i]);
        float2 v = __ldg(&F2[(size_t)s0 * 32 + lane]);
        ax += v.x;
        ay += v.y;
    }
    reinterpret_cast<float2*>(S[warp])[lane] = make_float2(ax, ay);

    // ---- Load K column (independent of smem; overlaps with sync) ----
    int u = threadIdx.x & 63;
    int g = threadIdx.x >> 6;  // 0..3 -> rows 2g, 2g+1
    float Kreg[64];
#pragma unroll
    for (int k = 0; k < 64; k++) Kreg[k] = __ldg(&Kmat[k * U_DIM + u]);
    float b = __ldg(&bias[u]);

    __syncthreads();

    // ---- Phase B: out[row] = S[row] . K[:,u] + b ----
    const float4* R0 = reinterpret_cast<const float4*>(S[2 * g + 0]);
    const float4* R1 = reinterpret_cast<const float4*>(S[2 * g + 1]);
    float acc0 = 0.f, acc1 = 0.f;
#pragma unroll
    for (int k4 = 0; k4 < 16; k4++) {
        float4 x = R0[k4];
        float4 y = R1[k4];
        acc0 = fmaf(x.x, Kreg[4 * k4 + 0],
               fmaf(x.y, Kreg[4 * k4 + 1],
               fmaf(x.z, Kreg[4 * k4 + 2],
               fmaf(x.w, Kreg[4 * k4 + 3], acc0))));
        acc1 = fmaf(y.x, Kreg[4 * k4 + 0],
               fmaf(y.y, Kreg[4 * k4 + 1],
               fmaf(y.z, Kreg[4 * k4 + 2],
               fmaf(y.w, Kreg[4 * k4 + 3], acc1))));
    }

    size_t rowA = ((size_t)blockIdx.x * 8 + 2 * g) * U_DIM;
    out[rowA + u]         = acc0 + b;
    out[rowA + U_DIM + u] = acc1 + b;
}

// ---------------------------------------------------------------------------
// Launch pipeline (graph-capturable: kernels only, no sync, no allocs).
// ---------------------------------------------------------------------------
extern "C" void kernel_launch(void* const* d_in, const int* in_sizes, int n_in,
                              void* d_out, int out_size) {
    const float* feat = (const float*)d_in[0];   // [E, 64] fp32
    const int*   nbr  = (const int*)d_in[1];     // [P, 2]  int32
    const float* Kmat = (const float*)d_in[2];   // [64, 64] fp32
    const float* bias = (const float*)d_in[3];   // [64] fp32
    float* out = (float*)d_out;                  // [E, 64] fp32

    k_zero_cnt<<<(E_CNT / 4 + 255) / 256, 256>>>();
    k_hist<<<P_CNT / 256, 256>>>((const int2*)nbr);
    k_scan_block<<<NSCAN, SCAN_BLK>>>();
    k_scan_sums<<<1, SCAN_BLK>>>();
    k_scan_add<<<(E_CNT + 255) / 256, 256>>>();
    k_reorder<<<P_CNT / 256, 256>>>((const int2*)nbr);
    k_fused<<<E_CNT / 8, 256>>>((const float2*)feat, Kmat, bias, out);
}